// round 5
// baseline (speedup 1.0000x reference)
#include <cuda_runtime.h>
#include <cuda_bf16.h>
#include <cstdint>

#define N_MAX 50000
#define DIM 128

__device__ __align__(16) float g_h[N_MAX * DIM];
__device__ __align__(16) float g_agg[N_MAX * DIM];
__device__ float g_deg[N_MAX];
__device__ int   g_is64;
// pre-split tf32 weights: [0]=W1, [1]=W2
__device__ __align__(16) float g_Wh[2][DIM * DIM];
__device__ __align__(16) float g_Wl[2][DIM * DIM];

// ---------------------------------------------------------------------------
__device__ __forceinline__ uint32_t f2tf32(float x)
{
    uint32_t r;
    asm("cvt.rna.tf32.f32 %0, %1;" : "=r"(r) : "f"(x));
    return r;
}

__device__ __forceinline__ void mma8(float* d,
    uint32_t a0, uint32_t a1, uint32_t a2, uint32_t a3,
    uint32_t b0, uint32_t b1)
{
    asm volatile(
        "mma.sync.aligned.m16n8k8.row.col.f32.tf32.tf32.f32 "
        "{%0,%1,%2,%3}, {%4,%5,%6,%7}, {%8,%9}, {%0,%1,%2,%3};"
        : "+f"(d[0]), "+f"(d[1]), "+f"(d[2]), "+f"(d[3])
        : "r"(a0), "r"(a1), "r"(a2), "r"(a3), "r"(b0), "r"(b1));
}

// ---------------------------------------------------------------------------
// Edge-index dtype probe (int64 data has all odd 32-bit words == 0).
// ---------------------------------------------------------------------------
__global__ void detect_kernel(const int* __restrict__ ei_words)
{
    if (threadIdx.x == 0) {
        int all_zero = 1;
        for (int i = 0; i < 128; i++)
            if (ei_words[2 * i + 1] != 0) { all_zero = 0; break; }
        g_is64 = all_zero;
    }
}

// ---------------------------------------------------------------------------
// One-shot Markidis split of both weight matrices into g_Wh / g_Wl.
// ---------------------------------------------------------------------------
__global__ void split_kernel(const float* __restrict__ W1,
                             const float* __restrict__ W2)
{
    int i = blockIdx.x * blockDim.x + threadIdx.x;   // 0 .. 32767
    int w = i >> 14;
    int j = i & 16383;
    float v = w ? __ldg(W2 + j) : __ldg(W1 + j);
    uint32_t hi = f2tf32(v);
    g_Wh[w][j] = __uint_as_float(hi);
    g_Wl[w][j] = __uint_as_float(f2tf32(v - __uint_as_float(hi)));
}

// ---------------------------------------------------------------------------
// tf32 tensor-core GEMM, 3-term Markidis (~fp32 accuracy):
//   OUT[N,128] = act( IN[N,128] @ W[128,128]^T + b )
// MODE 0: IN = X, relu, zero g_agg/g_deg in epilogue.  MODE 1: IN = agg/deg+h.
// BM=64, BN=128, BK=16, 256 thr (8 warps: 4 along M x 2 along N).
// Warp tile 16x64 -> acc = 32 regs. Register-prefetch pipeline over k-tiles.
// Smem stride 20 -> fragment LDS conflict-free; fills are aligned STS.128.
// ---------------------------------------------------------------------------
template <int MODE, int WIDX>
__global__ void __launch_bounds__(256, 3)
gemm_tc(const float* __restrict__ X, const float* __restrict__ bias,
        float* __restrict__ OUT, int N)
{
    constexpr int LDSH = 20;
    __shared__ float Ahi[64 * LDSH], Alo[64 * LDSH];
    __shared__ float Whi[128 * LDSH], Wlo[128 * LDSH];
    __shared__ float invd[64];

    const int t    = threadIdx.x;
    const int lane = t & 31;
    const int warp = t >> 5;
    const int g    = lane >> 2;
    const int tig  = lane & 3;
    const int wm   = warp & 3;          // 4 warps along M (16 rows each)
    const int wn   = warp >> 2;         // 2 warps along N (64 cols each)
    const int row0 = blockIdx.x * 64;

    float acc[8][4];
#pragma unroll
    for (int nt = 0; nt < 8; nt++)
#pragma unroll
        for (int c = 0; c < 4; c++) acc[nt][c] = 0.f;

    if (MODE == 1) {
        if (t < 64) {
            int r = row0 + t;
            float d = (r < N) ? g_deg[r] : 1.f;
            invd[t] = 1.f / fmaxf(d, 1.f);
        }
        __syncthreads();
    }

    // fill ownership
    const int fr = t >> 2;              // A row 0..63
    const int fs = (t & 3) * 4;         // k offset {0,4,8,12}
    const int gr = row0 + fr;
    const int wr0 = t >> 2, ws0 = (t & 3) * 4;            // W row 0..63
    const int wr1 = wr0 + 64, ws1 = ws0;                  // W row 64..127

    // prefetch registers
    float4 a_p0 = make_float4(0.f, 0.f, 0.f, 0.f), a_p1 = a_p0;
    float4 w_h0, w_l0, w_h1, w_l1;

    auto prefetch = [&](int k0) {
        if (gr < N) {
            if (MODE == 0) {
                a_p0 = __ldg((const float4*)(X + (size_t)gr * DIM + k0 + fs));
            } else {
                a_p0 = *(const float4*)(g_agg + (size_t)gr * DIM + k0 + fs);
                a_p1 = *(const float4*)(g_h   + (size_t)gr * DIM + k0 + fs);
            }
        } else {
            a_p0 = make_float4(0.f, 0.f, 0.f, 0.f);
            a_p1 = a_p0;
        }
        w_h0 = *(const float4*)(&g_Wh[WIDX][wr0 * DIM + k0 + ws0]);
        w_l0 = *(const float4*)(&g_Wl[WIDX][wr0 * DIM + k0 + ws0]);
        w_h1 = *(const float4*)(&g_Wh[WIDX][wr1 * DIM + k0 + ws1]);
        w_l1 = *(const float4*)(&g_Wl[WIDX][wr1 * DIM + k0 + ws1]);
    };

    prefetch(0);

    for (int k0 = 0; k0 < DIM; k0 += 16) {
        // ---- convert A, store tiles ----
        float v[4];
        if (MODE == 0) {
            v[0] = a_p0.x; v[1] = a_p0.y; v[2] = a_p0.z; v[3] = a_p0.w;
        } else {
            float s = invd[fr];
            v[0] = fmaf(a_p0.x, s, a_p1.x); v[1] = fmaf(a_p0.y, s, a_p1.y);
            v[2] = fmaf(a_p0.z, s, a_p1.z); v[3] = fmaf(a_p0.w, s, a_p1.w);
        }
        float4 ah4, al4;
        {
            uint32_t h0 = f2tf32(v[0]), h1 = f2tf32(v[1]),
                     h2 = f2tf32(v[2]), h3 = f2tf32(v[3]);
            ah4 = make_float4(__uint_as_float(h0), __uint_as_float(h1),
                              __uint_as_float(h2), __uint_as_float(h3));
            al4 = make_float4(
                __uint_as_float(f2tf32(v[0] - __uint_as_float(h0))),
                __uint_as_float(f2tf32(v[1] - __uint_as_float(h1))),
                __uint_as_float(f2tf32(v[2] - __uint_as_float(h2))),
                __uint_as_float(f2tf32(v[3] - __uint_as_float(h3))));
        }
        *(float4*)&Ahi[fr * LDSH + fs] = ah4;
        *(float4*)&Alo[fr * LDSH + fs] = al4;
        *(float4*)&Whi[wr0 * LDSH + ws0] = w_h0;
        *(float4*)&Wlo[wr0 * LDSH + ws0] = w_l0;
        *(float4*)&Whi[wr1 * LDSH + ws1] = w_h1;
        *(float4*)&Wlo[wr1 * LDSH + ws1] = w_l1;
        __syncthreads();

        if (k0 + 16 < DIM) prefetch(k0 + 16);   // LDGs fly during MMA section

        // ---- MMA ----
#pragma unroll
        for (int kk = 0; kk < 16; kk += 8) {
            const int r_ = wm * 16 + g;
            const int c0 = kk + tig, c1 = kk + tig + 4;
            uint32_t ah0 = __float_as_uint(Ahi[r_ * LDSH + c0]);
            uint32_t ah1 = __float_as_uint(Ahi[(r_ + 8) * LDSH + c0]);
            uint32_t ah2 = __float_as_uint(Ahi[r_ * LDSH + c1]);
            uint32_t ah3 = __float_as_uint(Ahi[(r_ + 8) * LDSH + c1]);
            uint32_t al0 = __float_as_uint(Alo[r_ * LDSH + c0]);
            uint32_t al1 = __float_as_uint(Alo[(r_ + 8) * LDSH + c0]);
            uint32_t al2 = __float_as_uint(Alo[r_ * LDSH + c1]);
            uint32_t al3 = __float_as_uint(Alo[(r_ + 8) * LDSH + c1]);
#pragma unroll
            for (int nt = 0; nt < 8; nt++) {
                const int n_ = wn * 64 + nt * 8 + g;
                uint32_t bh0 = __float_as_uint(Whi[n_ * LDSH + c0]);
                uint32_t bh1 = __float_as_uint(Whi[n_ * LDSH + c1]);
                uint32_t bl0 = __float_as_uint(Wlo[n_ * LDSH + c0]);
                uint32_t bl1 = __float_as_uint(Wlo[n_ * LDSH + c1]);
                mma8(acc[nt], ah0, ah1, ah2, ah3, bh0, bh1);
                mma8(acc[nt], ah0, ah1, ah2, ah3, bl0, bl1);
                mma8(acc[nt], al0, al1, al2, al3, bh0, bh1);
            }
        }
        __syncthreads();
    }

    // ---- epilogue: c0:(g,2t) c1:(g,2t+1) c2:(g+8,2t) c3:(g+8,2t+1) ----
#pragma unroll
    for (int nt = 0; nt < 8; nt++) {
        int c = wn * 64 + nt * 8 + 2 * tig;
        float b0 = __ldg(bias + c), b1 = __ldg(bias + c + 1);
        int r_ = row0 + wm * 16 + g;
        if (r_ < N) {
            float o0 = acc[nt][0] + b0, o1 = acc[nt][1] + b1;
            if (MODE == 0) { o0 = fmaxf(o0, 0.f); o1 = fmaxf(o1, 0.f); }
            *(float2*)(OUT + (size_t)r_ * DIM + c) = make_float2(o0, o1);
        }
        int r2 = r_ + 8;
        if (r2 < N) {
            float o2 = acc[nt][2] + b0, o3 = acc[nt][3] + b1;
            if (MODE == 0) { o2 = fmaxf(o2, 0.f); o3 = fmaxf(o3, 0.f); }
            *(float2*)(OUT + (size_t)r2 * DIM + c) = make_float2(o2, o3);
        }
    }

    if (MODE == 0) {
        // zero aggregation buffers for the edge kernel
        const float4 z4 = make_float4(0.f, 0.f, 0.f, 0.f);
#pragma unroll
        for (int s = 0; s < 8; s++) {
            int idx = t + s * 256;          // 64 rows x 32 float4 = 2048 slots
            int r = idx >> 5;
            if (row0 + r < N)
                ((float4*)(g_agg + (size_t)(row0 + r) * DIM))[idx & 31] = z4;
        }
        if (t < 64 && row0 + t < N) g_deg[row0 + t] = 0.f;
    }
}

// ---------------------------------------------------------------------------
// Edge scatter: one warp per edge; lane = one float4 of the 128-float row.
// red.global.add.v4.f32 -> 12.8M vector reductions; h (25.6MB) L2-resident.
// ---------------------------------------------------------------------------
__global__ void __launch_bounds__(256)
edge_kernel(const void* __restrict__ ei_raw, int nE)
{
    int gid  = blockIdx.x * blockDim.x + threadIdx.x;
    int e    = gid >> 5;
    int lane = gid & 31;
    if (e >= nE) return;

    int src, dst;
    if (g_is64) {
        const long long* ei = (const long long*)ei_raw;
        src = (int)ei[e];
        dst = (int)ei[nE + e];
    } else {
        const int* ei = (const int*)ei_raw;
        src = ei[e];
        dst = ei[nE + e];
    }

    const float4 v = __ldg((const float4*)(g_h + (size_t)src * DIM) + lane);
    float4* p = (float4*)(g_agg + (size_t)dst * DIM) + lane;
    asm volatile("red.global.add.v4.f32 [%0], {%1,%2,%3,%4};"
                 :: "l"(p), "f"(v.x), "f"(v.y), "f"(v.z), "f"(v.w)
                 : "memory");
    if (lane == 0) atomicAdd(&g_deg[dst], 1.0f);
}

// ---------------------------------------------------------------------------
extern "C" void kernel_launch(void* const* d_in, const int* in_sizes, int n_in,
                              void* d_out, int out_size)
{
    const float* x  = (const float*)d_in[0];
    const void*  ei = d_in[1];
    const float* W1 = (const float*)d_in[2];
    const float* b1 = (const float*)d_in[3];
    const float* W2 = (const float*)d_in[4];
    const float* b2 = (const float*)d_in[5];
    float*       out = (float*)d_out;

    const int N  = in_sizes[0] / DIM;      // 50000
    const int nE = in_sizes[1] / 2;        // 400000

    float* h_ptr;
    cudaGetSymbolAddress((void**)&h_ptr, g_h);

    const int gemm_blocks = (N + 63) / 64;

    // 0) probe edge dtype; split W1/W2 into tf32 hi/lo
    detect_kernel<<<1, 32>>>((const int*)ei);
    split_kernel<<<128, 256>>>(W1, W2);

    // 1) h = relu(x @ W1^T + b1); zero agg/deg
    gemm_tc<0, 0><<<gemm_blocks, 256>>>(x, b1, h_ptr, N);

    // 2) scatter-add h[src] into agg[dst], count degrees
    const long long edge_threads = (long long)nE * 32;
    edge_kernel<<<(int)((edge_threads + 255) / 256), 256>>>(ei, nE);

    // 3) out = (agg/deg + h) @ W2^T + b2
    gemm_tc<1, 1><<<gemm_blocks, 256>>>(nullptr, b2, out, N);
}